// round 11
// baseline (speedup 1.0000x reference)
#include <cuda_runtime.h>

// Problem constants (fixed by the dataset):
//   x_in:    [N,1,H,W]   float32
//   filters: [N,81,H,W]  float32
//   bias:    [N,1,H,W]   float32
//   out:     [N,1,H,W]   float32
// out = sum_k patches(x)*filters + bias, 9x9 window, pad 4, dilation 1.

#define KSZ 9
#define PADR 4
#define NB 4
#define HH 544
#define WW 960
#define PLANE (HH * WW)          // 522240

#define TILE_W 128               // 32 threads * 4 outputs
#define TILE_H 4                 // halved vs R7: finer tail granularity

// R7-proven structure: x-window loads BEFORE filter batch (f and xv not
// simultaneously live -> no spill; R9 proved filters-first pins 64 regs and
// spills). 128-thread CTAs, ~56 regs -> ~9 CTAs/SM resident.
__global__ __launch_bounds__(128)
void dfl_kernel(const float* __restrict__ x,
                const float* __restrict__ filt,
                const float* __restrict__ bias,
                float* __restrict__ out)
{
    const int n  = blockIdx.z;
    const int bw = blockIdx.x * TILE_W;
    const int bh = blockIdx.y * TILE_H;
    const int tx = threadIdx.x;           // 0..31
    const int ty = threadIdx.y;           // 0..3

    const int w = bw + tx * 4;            // first of 4 output cols
    const int h = bh + ty;                // output row (544 % 4 == 0)
    if (w >= WW) return;                  // last block column half-active

    const float* __restrict__ xn = x + n * PLANE;
    const int pix = h * WW + w;

    // Interior CTA: the 12-wide window [w-4, w+8) x rows [bh-4, bh+TILE_H+4)
    // never leaves the image for ANY thread of the block. Uniform per CTA.
    const bool interior = (bh >= PADR) && (bh + TILE_H + PADR <= HH) &&
                          (bw >= PADR) && (bw + TILE_W + PADR <= WW);

    const float4 b4 = __ldcs(reinterpret_cast<const float4*>(bias + n * PLANE + pix));
    float a0 = b4.x, a1 = b4.y, a2 = b4.z, a3 = b4.w;

    const float* __restrict__ fbase = filt + (n * (KSZ * KSZ)) * PLANE + pix;

    #pragma unroll
    for (int dy = 0; dy < KSZ; ++dy) {
        // 12-wide x window for this row: cols [w-4 .. w+7], all 16B-aligned.
        // L1/L2 hits; loaded first so xv drains into FMAs while f lands.
        float xv[12];
        if (interior) {
            const float* xr = xn + (h + dy - PADR) * WW + (w - PADR);
            const float4 t0 = *reinterpret_cast<const float4*>(xr + 0);
            const float4 t1 = *reinterpret_cast<const float4*>(xr + 4);
            const float4 t2 = *reinterpret_cast<const float4*>(xr + 8);
            xv[0] = t0.x; xv[1]  = t0.y; xv[2]  = t0.z; xv[3]  = t0.w;
            xv[4] = t1.x; xv[5]  = t1.y; xv[6]  = t1.z; xv[7]  = t1.w;
            xv[8] = t2.x; xv[9]  = t2.y; xv[10] = t2.z; xv[11] = t2.w;
        } else {
            const int gr = h + dy - PADR;
            #pragma unroll
            for (int j = 0; j < 12; ++j) {
                const int gc = w - PADR + j;
                xv[j] = ((unsigned)gr < (unsigned)HH && (unsigned)gc < (unsigned)WW)
                            ? __ldg(xn + gr * WW + gc) : 0.0f;
            }
        }

        // Full-row filter batch: 9 independent streaming LDG.128 (MLP >= 9),
        // evict-first so filters never displace x in L2.
        float4 f[KSZ];
        #pragma unroll
        for (int dx = 0; dx < KSZ; ++dx)
            f[dx] = __ldcs(reinterpret_cast<const float4*>(fbase + (dy * KSZ + dx) * PLANE));

        #pragma unroll
        for (int dx = 0; dx < KSZ; ++dx) {
            a0 = fmaf(xv[dx + 0], f[dx].x, a0);
            a1 = fmaf(xv[dx + 1], f[dx].y, a1);
            a2 = fmaf(xv[dx + 2], f[dx].z, a2);
            a3 = fmaf(xv[dx + 3], f[dx].w, a3);
        }
    }

    __stcs(reinterpret_cast<float4*>(out + n * PLANE + pix),
           make_float4(a0, a1, a2, a3));
}

extern "C" void kernel_launch(void* const* d_in, const int* in_sizes, int n_in,
                              void* d_out, int out_size)
{
    const float* x    = (const float*)d_in[0];   // x_in
    const float* filt = (const float*)d_in[1];   // filters
    const float* bias = (const float*)d_in[2];   // filters_biases
    float* out        = (float*)d_out;

    dim3 block(32, 4, 1);
    dim3 grid((WW + TILE_W - 1) / TILE_W,   // 8 (last block column half-active)
              HH / TILE_H,                  // 136
              NB);                          // 4
    dfl_kernel<<<grid, block>>>(x, filt, bias, out);
}

// round 12
// speedup vs baseline: 1.0397x; 1.0397x over previous
#include <cuda_runtime.h>

// Problem constants (fixed by the dataset):
//   x_in:    [N,1,H,W]   float32
//   filters: [N,81,H,W]  float32
//   bias:    [N,1,H,W]   float32
//   out:     [N,1,H,W]   float32
// out = sum_k patches(x)*filters + bias, 9x9 window, pad 4, dilation 1.

#define KSZ 9
#define PADR 4
#define NB 4
#define HH 544
#define WW 960
#define PLANE (HH * WW)          // 522240

#define TILE_W 128               // 32 threads * 4 outputs
#define TILE_H 8

// R7-proven config: 256 threads, 4 CTAs/SM (64-reg budget), x-window loads
// BEFORE the filter batch (f and xv not simultaneously live -> no spill).
// New in this round: 3-tier x path -- out-of-image rows cost zero loads,
// col-safe threads (30/32 even in edge CTAs) take the vector path, and only
// the 2 edge threads per row ever touch the scalar fallback. This unclogs
// the LSU in border CTAs so their filter-load duty cycle matches interior.
__global__ __launch_bounds__(256, 4)
void dfl_kernel(const float* __restrict__ x,
                const float* __restrict__ filt,
                const float* __restrict__ bias,
                float* __restrict__ out)
{
    const int n  = blockIdx.z;
    const int bw = blockIdx.x * TILE_W;
    const int bh = blockIdx.y * TILE_H;
    const int tx = threadIdx.x;           // 0..31
    const int ty = threadIdx.y;           // 0..7

    const int w = bw + tx * 4;            // first of 4 output cols
    const int h = bh + ty;                // output row (544 % 8 == 0)
    if (w >= WW) return;                  // last block column half-active

    const float* __restrict__ xn = x + n * PLANE;
    const int pix = h * WW + w;

    // Per-thread column safety for the 12-wide window [w-4, w+8).
    const bool colsafe = (w >= PADR) && (w + 8 <= WW);

    const float4 b4 = __ldcs(reinterpret_cast<const float4*>(bias + n * PLANE + pix));
    float a0 = b4.x, a1 = b4.y, a2 = b4.z, a3 = b4.w;

    const float* __restrict__ fbase = filt + (n * (KSZ * KSZ)) * PLANE + pix;

    #pragma unroll
    for (int dy = 0; dy < KSZ; ++dy) {
        // 12-wide x window for this row: cols [w-4 .. w+7], 16B-aligned.
        // Loaded first so xv drains into FMAs while the filter batch lands.
        float xv[12];
        const int gr = h + dy - PADR;
        if ((unsigned)gr < (unsigned)HH) {
            if (colsafe) {
                const float* xr = xn + gr * WW + (w - PADR);
                const float4 t0 = *reinterpret_cast<const float4*>(xr + 0);
                const float4 t1 = *reinterpret_cast<const float4*>(xr + 4);
                const float4 t2 = *reinterpret_cast<const float4*>(xr + 8);
                xv[0] = t0.x; xv[1]  = t0.y; xv[2]  = t0.z; xv[3]  = t0.w;
                xv[4] = t1.x; xv[5]  = t1.y; xv[6]  = t1.z; xv[7]  = t1.w;
                xv[8] = t2.x; xv[9]  = t2.y; xv[10] = t2.z; xv[11] = t2.w;
            } else {
                // Only w=0 or w=956 threads (2 per row) ever take this path.
                #pragma unroll
                for (int j = 0; j < 12; ++j) {
                    const int gc = w - PADR + j;
                    xv[j] = ((unsigned)gc < (unsigned)WW)
                                ? __ldg(xn + gr * WW + gc) : 0.0f;
                }
            }
        } else {
            #pragma unroll
            for (int j = 0; j < 12; ++j) xv[j] = 0.0f;   // no loads at all
        }

        // Full-row filter batch: 9 independent streaming LDG.128 (MLP >= 9),
        // evict-first so filters never displace x in L2.
        float4 f[KSZ];
        #pragma unroll
        for (int dx = 0; dx < KSZ; ++dx)
            f[dx] = __ldcs(reinterpret_cast<const float4*>(fbase + (dy * KSZ + dx) * PLANE));

        #pragma unroll
        for (int dx = 0; dx < KSZ; ++dx) {
            a0 = fmaf(xv[dx + 0], f[dx].x, a0);
            a1 = fmaf(xv[dx + 1], f[dx].y, a1);
            a2 = fmaf(xv[dx + 2], f[dx].z, a2);
            a3 = fmaf(xv[dx + 3], f[dx].w, a3);
        }
    }

    __stcs(reinterpret_cast<float4*>(out + n * PLANE + pix),
           make_float4(a0, a1, a2, a3));
}

extern "C" void kernel_launch(void* const* d_in, const int* in_sizes, int n_in,
                              void* d_out, int out_size)
{
    const float* x    = (const float*)d_in[0];   // x_in
    const float* filt = (const float*)d_in[1];   // filters
    const float* bias = (const float*)d_in[2];   // filters_biases
    float* out        = (float*)d_out;

    dim3 block(32, 8, 1);
    dim3 grid((WW + TILE_W - 1) / TILE_W,   // 8 (last block column half-active)
              HH / TILE_H,                  // 68
              NB);                          // 4
    dfl_kernel<<<grid, block>>>(x, filt, bias, out);
}

// round 13
// speedup vs baseline: 1.0426x; 1.0028x over previous
#include <cuda_runtime.h>

// Problem constants (fixed by the dataset):
//   x_in:    [N,1,H,W]   float32
//   filters: [N,81,H,W]  float32
//   bias:    [N,1,H,W]   float32
//   out:     [N,1,H,W]   float32
// out = sum_k patches(x)*filters + sum-over-window, add per-pixel bias.

#define KSZ 9
#define PADR 4
#define NB 4
#define HH 544
#define WW 960
#define PLANE (HH * WW)          // 522240

#define TILE_W 64                // 32 threads * 2 outputs (960/64 = 15 exact)
#define TILE_H 8

// 2 outputs/thread: halves bytes-per-warp (20.7KB) to cut the end-of-kernel
// completion-spread loss (~14% -> ~7% predicted). f[9] is float2 (18 regs),
// so a 51-reg cap (5 CTAs/SM) fits without the R8-style spill.
__global__ __launch_bounds__(256, 5)
void dfl_kernel(const float* __restrict__ x,
                const float* __restrict__ filt,
                const float* __restrict__ bias,
                float* __restrict__ out)
{
    const int n  = blockIdx.z;
    const int bw = blockIdx.x * TILE_W;
    const int bh = blockIdx.y * TILE_H;
    const int tx = threadIdx.x;           // 0..31
    const int ty = threadIdx.y;           // 0..7

    const int w = bw + tx * 2;            // first of 2 output cols (even)
    const int h = bh + ty;                // output row (544 % 8 == 0)

    const float* __restrict__ xn = x + n * PLANE;
    const int pix = h * WW + w;

    // Per-thread column safety for the 10-wide window [w-4, w+6).
    const bool colsafe = (w >= PADR) && (w + 6 <= WW);

    const float2 b2 = __ldcs(reinterpret_cast<const float2*>(bias + n * PLANE + pix));
    float a0 = b2.x, a1 = b2.y;

    const float* __restrict__ fbase = filt + (n * (KSZ * KSZ)) * PLANE + pix;

    #pragma unroll
    for (int dy = 0; dy < KSZ; ++dy) {
        // 10-wide x window for this row: cols [w-4 .. w+5], all 8B-aligned.
        float xv[10];
        const int gr = h + dy - PADR;
        if ((unsigned)gr < (unsigned)HH) {
            if (colsafe) {
                const float* xr = xn + gr * WW + (w - PADR);
                const float2 p0 = *reinterpret_cast<const float2*>(xr + 0);
                const float2 p1 = *reinterpret_cast<const float2*>(xr + 2);
                const float2 p2 = *reinterpret_cast<const float2*>(xr + 4);
                const float2 p3 = *reinterpret_cast<const float2*>(xr + 6);
                const float2 p4 = *reinterpret_cast<const float2*>(xr + 8);
                xv[0] = p0.x; xv[1] = p0.y; xv[2] = p1.x; xv[3] = p1.y;
                xv[4] = p2.x; xv[5] = p2.y; xv[6] = p3.x; xv[7] = p3.y;
                xv[8] = p4.x; xv[9] = p4.y;
            } else {
                // Only threads with w in {0,2} or {956,958} ever land here.
                #pragma unroll
                for (int j = 0; j < 10; ++j) {
                    const int gc = w - PADR + j;
                    xv[j] = ((unsigned)gc < (unsigned)WW)
                                ? __ldg(xn + gr * WW + gc) : 0.0f;
                }
            }
        } else {
            #pragma unroll
            for (int j = 0; j < 10; ++j) xv[j] = 0.0f;   // no loads at all
        }

        // Full-row filter batch: 9 independent streaming LDG.64 (MLP 9),
        // evict-first so filters never displace x in L2.
        float2 f[KSZ];
        #pragma unroll
        for (int dx = 0; dx < KSZ; ++dx)
            f[dx] = __ldcs(reinterpret_cast<const float2*>(fbase + (dy * KSZ + dx) * PLANE));

        #pragma unroll
        for (int dx = 0; dx < KSZ; ++dx) {
            a0 = fmaf(xv[dx + 0], f[dx].x, a0);
            a1 = fmaf(xv[dx + 1], f[dx].y, a1);
        }
    }

    __stcs(reinterpret_cast<float2*>(out + n * PLANE + pix), make_float2(a0, a1));
}

extern "C" void kernel_launch(void* const* d_in, const int* in_sizes, int n_in,
                              void* d_out, int out_size)
{
    const float* x    = (const float*)d_in[0];   // x_in
    const float* filt = (const float*)d_in[1];   // filters
    const float* bias = (const float*)d_in[2];   // filters_biases
    float* out        = (float*)d_out;

    dim3 block(32, 8, 1);
    dim3 grid(WW / TILE_W,   // 15 (exact)
              HH / TILE_H,   // 68
              NB);           // 4
    dfl_kernel<<<grid, block>>>(x, filt, bias, out);
}